// round 1
// baseline (speedup 1.0000x reference)
#include <cuda_runtime.h>

// Problem constants
static constexpr int   N_PTS   = 16384;
static constexpr int   C_DIM   = 16;
static constexpr int   H_DIM   = 32;
static constexpr int   KNN     = 9;
static constexpr int   N_STEPS = 2;
static constexpr float UPD_RATE = 1e-4f;

// Spatial grid constants
static constexpr int   GG  = 128;          // grid is GG x GG
static constexpr float GB  = 5.0f;         // coords binned over [-GB, GB]
static constexpr int   CAP = 64;           // max points stored per cell (peak density ~16)
static constexpr float CS  = 2.0f * GB / GG;       // cell size
static constexpr float INV_CS = GG / (2.0f * GB);

// Scratch (device globals: allocation-free per harness rules)
__device__ __align__(16) float  g_x [N_PTS * C_DIM];
__device__ __align__(16) float  g_ha[N_PTS * H_DIM];
__device__ __align__(16) float  g_hb[N_PTS * H_DIM];
__device__ int    g_idx[N_PTS * KNN];
__device__ int    g_cnt[GG * GG];
__device__ float4 g_pts[GG * GG * CAP];    // (x, y, bitcast(id), 0)

__device__ __forceinline__ int cell_coord(float v) {
    int c = (int)floorf((v + GB) * INV_CS);
    c = c < 0 ? 0 : c;
    c = c > GG - 1 ? GG - 1 : c;
    return c;
}

// ---------------------------------------------------------------------------
__global__ void k_copy_in(const float* __restrict__ src) {
    int i = blockIdx.x * blockDim.x + threadIdx.x;
    if (i < N_PTS * C_DIM) g_x[i] = src[i];
}

__global__ void k_zero_cnt() {
    int i = blockIdx.x * blockDim.x + threadIdx.x;
    if (i < GG * GG) g_cnt[i] = 0;
}

__global__ void k_binfill() {
    int i = blockIdx.x * blockDim.x + threadIdx.x;
    if (i >= N_PTS) return;
    float px = g_x[i * C_DIM + 0];
    float py = g_x[i * C_DIM + 1];
    int cx = cell_coord(px);
    int cy = cell_coord(py);
    int b = cy * GG + cx;
    int s = atomicAdd(&g_cnt[b], 1);
    if (s < CAP) g_pts[b * CAP + s] = make_float4(px, py, __int_as_float(i), 0.0f);
}

// ---------------------------------------------------------------------------
// kNN via expanding Chebyshev rings over the spatial grid.
__global__ void k_knn() {
    int q = blockIdx.x * blockDim.x + threadIdx.x;
    if (q >= N_PTS) return;

    const float qx = g_x[q * C_DIM + 0];
    const float qy = g_x[q * C_DIM + 1];
    const int cx = cell_coord(qx);
    const int cy = cell_coord(qy);

    const float INF = __int_as_float(0x7f800000);
    float bd[KNN];
    int   bi[KNN];
#pragma unroll
    for (int p = 0; p < KNN; ++p) { bd[p] = INF; bi[p] = q; }

    auto scan_cell = [&](int xx, int yy) {
        int b = yy * GG + xx;
        int cnt = g_cnt[b];
        cnt = cnt < CAP ? cnt : CAP;
        const float4* pp = &g_pts[b * CAP];
        for (int t = 0; t < cnt; ++t) {
            float4 p = pp[t];
            float dx = qx - p.x;
            float dy = qy - p.y;
            float d2 = __fadd_rn(__fmul_rn(dx, dx), __fmul_rn(dy, dy));
            if (d2 < bd[KNN - 1]) {
                float cd = d2;
                int   ci = __float_as_int(p.z);
#pragma unroll
                for (int pos = 0; pos < KNN; ++pos) {
                    if (cd < bd[pos]) {
                        float tf = bd[pos]; bd[pos] = cd; cd = tf;
                        int   ti = bi[pos]; bi[pos] = ci; ci = ti;
                    }
                }
            }
        }
    };

    for (int r = 0; r < GG; ++r) {
        if (r == 0) {
            scan_cell(cx, cy);
        } else {
            int x0 = cx - r, x1 = cx + r, y0 = cy - r, y1 = cy + r;
            int xa = x0 < 0 ? 0 : x0;
            int xb = x1 > GG - 1 ? GG - 1 : x1;
            for (int xx = xa; xx <= xb; ++xx) {
                if (y0 >= 0) scan_cell(xx, y0);
                if (y1 < GG) scan_cell(xx, y1);
            }
            int ya = (y0 + 1) < 0 ? 0 : (y0 + 1);
            int yb = (y1 - 1) > GG - 1 ? GG - 1 : (y1 - 1);
            for (int yy = ya; yy <= yb; ++yy) {
                if (x0 >= 0) scan_cell(x0, yy);
                if (x1 < GG) scan_cell(x1, yy);
            }
        }
        // After ring r, all unvisited points are at distance >= r*CS.
        float rim = (float)r * CS;
        if (bd[KNN - 1] <= rim * rim) break;
    }

#pragma unroll
    for (int p = 0; p < KNN; ++p) g_idx[q * KNN + p] = bi[p];
}

// ---------------------------------------------------------------------------
// One GCN layer: agg = mean over 9 neighbors of hin; out = agg @ W;
// optional ReLU; optional fused residual update (x += out * UPD_RATE, in place).
template <int CIN, int COUT, bool RELU, bool UPD>
__global__ void k_layer(const float* __restrict__ hin,
                        const float* __restrict__ W,
                        float* __restrict__ hout) {
    __shared__ float sW[CIN * COUT];
    for (int i = threadIdx.x; i < CIN * COUT; i += blockDim.x) sW[i] = W[i];
    __syncthreads();

    int n = blockIdx.x * blockDim.x + threadIdx.x;
    if (n >= N_PTS) return;

    float agg[CIN];
#pragma unroll
    for (int c = 0; c < CIN; ++c) agg[c] = 0.0f;

    const int* ip = g_idx + n * KNN;
#pragma unroll
    for (int k = 0; k < KNN; ++k) {
        const float4* row = (const float4*)(hin + ip[k] * CIN);
#pragma unroll
        for (int c4 = 0; c4 < CIN / 4; ++c4) {
            float4 v = row[c4];
            agg[4 * c4 + 0] += v.x;
            agg[4 * c4 + 1] += v.y;
            agg[4 * c4 + 2] += v.z;
            agg[4 * c4 + 3] += v.w;
        }
    }
#pragma unroll
    for (int c = 0; c < CIN; ++c) agg[c] *= (1.0f / 9.0f);

    float acc[COUT];
#pragma unroll
    for (int j = 0; j < COUT; ++j) acc[j] = 0.0f;
#pragma unroll
    for (int c = 0; c < CIN; ++c) {
        float a = agg[c];
#pragma unroll
        for (int j = 0; j < COUT; ++j) acc[j] = fmaf(a, sW[c * COUT + j], acc[j]);
    }

#pragma unroll
    for (int j = 0; j < COUT; ++j) {
        float v = acc[j];
        if (RELU) v = fmaxf(v, 0.0f);
        if (UPD)  v = hout[n * COUT + j] + v * UPD_RATE;  // in-place x update
        hout[n * COUT + j] = v;
    }
}

__global__ void k_writeout(float* __restrict__ out) {
    int i = blockIdx.x * blockDim.x + threadIdx.x;
    if (i < N_PTS * C_DIM) out[i] = g_x[i];
}

// ---------------------------------------------------------------------------
extern "C" void kernel_launch(void* const* d_in, const int* in_sizes, int n_in,
                              void* d_out, int out_size) {
    const float* seed = (const float*)d_in[0];
    const float* W1   = (const float*)d_in[1];
    const float* W2   = (const float*)d_in[2];
    const float* W3   = (const float*)d_in[3];
    const float* W4   = (const float*)d_in[4];
    // d_in[5] = n_steps, fixed at 2 by the problem setup.

    float *px, *pha, *phb;
    cudaGetSymbolAddress((void**)&px,  g_x);
    cudaGetSymbolAddress((void**)&pha, g_ha);
    cudaGetSymbolAddress((void**)&phb, g_hb);

    k_copy_in<<<(N_PTS * C_DIM + 255) / 256, 256>>>(seed);

    for (int s = 0; s < N_STEPS; ++s) {
        k_zero_cnt<<<(GG * GG + 255) / 256, 256>>>();
        k_binfill<<<N_PTS / 256, 256>>>();
        k_knn<<<N_PTS / 128, 128>>>();
        k_layer<16, 32, true,  false><<<N_PTS / 128, 128>>>(px,  W1, pha);
        k_layer<32, 32, true,  false><<<N_PTS / 128, 128>>>(pha, W2, phb);
        k_layer<32, 32, true,  false><<<N_PTS / 128, 128>>>(phb, W3, pha);
        k_layer<32, 16, false, true ><<<N_PTS / 128, 128>>>(pha, W4, px);
    }

    k_writeout<<<(N_PTS * C_DIM + 255) / 256, 256>>>((float*)d_out);
}

// round 2
// speedup vs baseline: 1.3477x; 1.3477x over previous
#include <cuda_runtime.h>

// Problem constants
static constexpr int   N_PTS   = 16384;
static constexpr int   C_DIM   = 16;
static constexpr int   H_DIM   = 32;
static constexpr int   KNN     = 9;
static constexpr int   N_STEPS = 2;
static constexpr float UPD_RATE = 1e-4f;

// Spatial grid constants (GG*GG == N_PTS so 16384-thread kernels can zero counts)
static constexpr int   GG  = 128;
static constexpr float GB  = 5.0f;
static constexpr int   CAP = 64;
static constexpr float CS  = 2.0f * GB / GG;
static constexpr float INV_CS = GG / (2.0f * GB);

// Scratch (device globals: allocation-free per harness rules)
__device__ __align__(16) float  g_x [N_PTS * C_DIM];
__device__ __align__(16) float  g_ha[N_PTS * H_DIM];
__device__ __align__(16) float  g_hb[N_PTS * H_DIM];
__device__ int    g_idx[N_PTS * KNN];
__device__ int    g_cnt[GG * GG];
__device__ float4 g_pts[GG * GG * CAP];    // (x, y, bitcast(id), 0)

__device__ __forceinline__ int cell_coord(float v) {
    int c = (int)floorf((v + GB) * INV_CS);
    c = c < 0 ? 0 : c;
    c = c > GG - 1 ? GG - 1 : c;
    return c;
}

__device__ __forceinline__ void bin_insert(float px, float py, int id) {
    int cx = cell_coord(px);
    int cy = cell_coord(py);
    int b = cy * GG + cx;
    int s = atomicAdd(&g_cnt[b], 1);
    if (s < CAP) g_pts[b * CAP + s] = make_float4(px, py, __int_as_float(id), 0.0f);
}

// ---------------------------------------------------------------------------
// copy seed -> g_x, and zero the cell counters for step 0
__global__ void k_copy_in(const float* __restrict__ src) {
    int i = blockIdx.x * blockDim.x + threadIdx.x;
    if (i < N_PTS * C_DIM) g_x[i] = src[i];
    if (i < GG * GG) g_cnt[i] = 0;
}

// bin fill for step 0 (coords already in g_x)
__global__ void k_binfill() {
    int i = blockIdx.x * blockDim.x + threadIdx.x;
    if (i >= N_PTS) return;
    bin_insert(g_x[i * C_DIM + 0], g_x[i * C_DIM + 1], i);
}

// ---------------------------------------------------------------------------
// Warp-per-query kNN via expanding Chebyshev rings.
// Lanes partition points within each cell; each lane keeps a sorted local
// top-9; ring termination by warp-summed count of candidates <= rim^2;
// final 9-way merge via u64 warp-min reduction.
__global__ void __launch_bounds__(256) k_knn() {
    int gtid = blockIdx.x * blockDim.x + threadIdx.x;
    int q    = gtid >> 5;
    int lane = gtid & 31;
    if (q >= N_PTS) return;

    const float qx = g_x[q * C_DIM + 0];
    const float qy = g_x[q * C_DIM + 1];
    const int cx = cell_coord(qx);
    const int cy = cell_coord(qy);

    const float INF = __int_as_float(0x7f800000);
    float bd[KNN];
    int   bi[KNN];
#pragma unroll
    for (int p = 0; p < KNN; ++p) { bd[p] = INF; bi[p] = q; }

    auto scan_cell = [&](int xx, int yy) {
        int b = yy * GG + xx;
        int cnt = g_cnt[b];
        cnt = cnt < CAP ? cnt : CAP;
        const float4* pp = &g_pts[b * CAP];
        for (int t = lane; t < cnt; t += 32) {
            float4 p = pp[t];
            float dx = qx - p.x;
            float dy = qy - p.y;
            float d2 = __fadd_rn(__fmul_rn(dx, dx), __fmul_rn(dy, dy));
            if (d2 < bd[KNN - 1]) {
                float cd = d2;
                int   ci = __float_as_int(p.z);
#pragma unroll
                for (int pos = 0; pos < KNN; ++pos) {
                    if (cd < bd[pos]) {
                        float tf = bd[pos]; bd[pos] = cd; cd = tf;
                        int   ti = bi[pos]; bi[pos] = ci; ci = ti;
                    }
                }
            }
        }
    };

    for (int r = 0; r < GG; ++r) {
        if (r == 0) {
            scan_cell(cx, cy);
        } else {
            int x0 = cx - r, x1 = cx + r, y0 = cy - r, y1 = cy + r;
            int xa = x0 < 0 ? 0 : x0;
            int xb = x1 > GG - 1 ? GG - 1 : x1;
            for (int xx = xa; xx <= xb; ++xx) {
                if (y0 >= 0) scan_cell(xx, y0);
                if (y1 < GG) scan_cell(xx, y1);
            }
            int ya = (y0 + 1) < 0 ? 0 : (y0 + 1);
            int yb = (y1 - 1) > GG - 1 ? GG - 1 : (y1 - 1);
            for (int yy = ya; yy <= yb; ++yy) {
                if (x0 >= 0) scan_cell(x0, yy);
                if (x1 < GG) scan_cell(x1, yy);
            }
            // Termination: if >= KNN candidates (warp-wide) lie within rim,
            // the global 9th-nearest is within rim; all unvisited cells are
            // farther than rim. (Any global-top-9 point is always retained
            // in its lane's local top-9, so the count is exact for this test.)
            float rim = (float)r * CS;
            float rim2 = rim * rim;
            int c = 0;
#pragma unroll
            for (int p = 0; p < KNN; ++p) c += (bd[p] <= rim2) ? 1 : 0;
#pragma unroll
            for (int off = 16; off > 0; off >>= 1)
                c += __shfl_xor_sync(0xffffffffu, c, off);
            if (c >= KNN) break;
        }
    }

    // Merge 32 sorted local lists -> global top-9.
#pragma unroll
    for (int sel = 0; sel < KNN; ++sel) {
        unsigned long long pack =
            ((unsigned long long)__float_as_uint(bd[0]) << 32) | (unsigned)bi[0];
        unsigned long long m = pack;
#pragma unroll
        for (int off = 16; off > 0; off >>= 1) {
            unsigned long long o = __shfl_xor_sync(0xffffffffu, m, off);
            m = o < m ? o : m;
        }
        unsigned matched = __ballot_sync(0xffffffffu, pack == m);
        if (lane == __ffs(matched) - 1) {
            // winner: pop head of local list
#pragma unroll
            for (int p = 0; p < KNN - 1; ++p) { bd[p] = bd[p + 1]; bi[p] = bi[p + 1]; }
            bd[KNN - 1] = INF;
            bi[KNN - 1] = q;
        }
        if (lane == 0) g_idx[q * KNN + sel] = (int)(unsigned)(m & 0xffffffffu);
    }
}

// ---------------------------------------------------------------------------
// One GCN layer. Optional fusions:
//   ZERO:    also zero g_cnt (for the NEXT step's binning; GG*GG == N_PTS)
//   UPD:     out = x + acc*UPD_RATE written in place (hout == g_x)
//   BINFILL: bin the freshly-updated coords (requires UPD)
//   WOUT:    also mirror the final x into out2 (harness d_out)
template <int CIN, int COUT, bool RELU, bool UPD, bool ZERO, bool BINFILL, bool WOUT>
__global__ void k_layer(const float* __restrict__ hin,
                        const float* __restrict__ W,
                        float* __restrict__ hout,
                        float* __restrict__ out2) {
    __shared__ float sW[CIN * COUT];
    for (int i = threadIdx.x; i < CIN * COUT; i += blockDim.x) sW[i] = W[i];
    __syncthreads();

    int n = blockIdx.x * blockDim.x + threadIdx.x;
    if (n >= N_PTS) return;

    if (ZERO) g_cnt[n] = 0;

    float agg[CIN];
#pragma unroll
    for (int c = 0; c < CIN; ++c) agg[c] = 0.0f;

    const int* ip = g_idx + n * KNN;
#pragma unroll
    for (int k = 0; k < KNN; ++k) {
        const float4* row = (const float4*)(hin + ip[k] * CIN);
#pragma unroll
        for (int c4 = 0; c4 < CIN / 4; ++c4) {
            float4 v = row[c4];
            agg[4 * c4 + 0] += v.x;
            agg[4 * c4 + 1] += v.y;
            agg[4 * c4 + 2] += v.z;
            agg[4 * c4 + 3] += v.w;
        }
    }
#pragma unroll
    for (int c = 0; c < CIN; ++c) agg[c] *= (1.0f / 9.0f);

    float acc[COUT];
#pragma unroll
    for (int j = 0; j < COUT; ++j) acc[j] = 0.0f;
#pragma unroll
    for (int c = 0; c < CIN; ++c) {
        float a = agg[c];
#pragma unroll
        for (int j = 0; j < COUT; ++j) acc[j] = fmaf(a, sW[c * COUT + j], acc[j]);
    }

    float nx = 0.0f, ny = 0.0f;
#pragma unroll
    for (int j = 0; j < COUT; ++j) {
        float v = acc[j];
        if (RELU) v = fmaxf(v, 0.0f);
        if (UPD)  v = hout[n * COUT + j] + v * UPD_RATE;  // in-place x update
        hout[n * COUT + j] = v;
        if (WOUT) out2[n * COUT + j] = v;
        if (BINFILL) {
            if (j == 0) nx = v;
            if (j == 1) ny = v;
        }
    }
    if (BINFILL) bin_insert(nx, ny, n);
}

// ---------------------------------------------------------------------------
extern "C" void kernel_launch(void* const* d_in, const int* in_sizes, int n_in,
                              void* d_out, int out_size) {
    const float* seed = (const float*)d_in[0];
    const float* W1   = (const float*)d_in[1];
    const float* W2   = (const float*)d_in[2];
    const float* W3   = (const float*)d_in[3];
    const float* W4   = (const float*)d_in[4];
    float* out = (float*)d_out;

    float *px, *pha, *phb;
    cudaGetSymbolAddress((void**)&px,  g_x);
    cudaGetSymbolAddress((void**)&pha, g_ha);
    cudaGetSymbolAddress((void**)&phb, g_hb);

    // step 0
    k_copy_in<<<(N_PTS * C_DIM + 255) / 256, 256>>>(seed);   // + zero counts
    k_binfill<<<N_PTS / 256, 256>>>();
    k_knn<<<(N_PTS * 32) / 256, 256>>>();
    k_layer<16, 32, true,  false, false, false, false><<<N_PTS / 128, 128>>>(px,  W1, pha, nullptr);
    k_layer<32, 32, true,  false, false, false, false><<<N_PTS / 128, 128>>>(pha, W2, phb, nullptr);
    k_layer<32, 32, true,  false, true,  false, false><<<N_PTS / 128, 128>>>(phb, W3, pha, nullptr); // zero counts for step 1
    k_layer<32, 16, false, true,  false, true,  false><<<N_PTS / 128, 128>>>(pha, W4, px,  nullptr); // x+= , bin new coords

    // step 1
    k_knn<<<(N_PTS * 32) / 256, 256>>>();
    k_layer<16, 32, true,  false, false, false, false><<<N_PTS / 128, 128>>>(px,  W1, pha, nullptr);
    k_layer<32, 32, true,  false, false, false, false><<<N_PTS / 128, 128>>>(pha, W2, phb, nullptr);
    k_layer<32, 32, true,  false, false, false, false><<<N_PTS / 128, 128>>>(phb, W3, pha, nullptr);
    k_layer<32, 16, false, true,  false, false, true ><<<N_PTS / 128, 128>>>(pha, W4, px,  out);     // x+= , writeout
}

// round 3
// speedup vs baseline: 4.0981x; 3.0407x over previous
#include <cuda_runtime.h>

// Problem constants
static constexpr int   N_PTS   = 16384;
static constexpr int   C_DIM   = 16;
static constexpr int   H_DIM   = 32;
static constexpr int   KNN     = 9;
static constexpr float UPD_RATE = 1e-4f;

// Spatial grid: 64x64 over [-5,5], ~4 pts/cell avg, ~64 at Gaussian peak.
static constexpr int   GG  = 64;
static constexpr float GB  = 5.0f;
static constexpr int   CAP = 128;              // peak cell ~64; huge safety margin
static constexpr float CS  = 2.0f * GB / GG;   // 0.15625
static constexpr float INV_CS = GG / (2.0f * GB);

// Scratch (device globals: allocation-free per harness rules)
__device__ __align__(16) float  g_x [N_PTS * C_DIM];
__device__ __align__(16) float  g_ha[N_PTS * H_DIM];
__device__ __align__(16) float  g_hb[N_PTS * H_DIM];
__device__ int    g_idx[N_PTS * KNN];
__device__ int    g_cnt[GG * GG];
__device__ float4 g_pts[GG * GG * CAP];        // (x, y, bitcast(id), 0)

__device__ __forceinline__ int cell_coord(float v) {
    int c = (int)floorf((v + GB) * INV_CS);
    c = c < 0 ? 0 : c;
    c = c > GG - 1 ? GG - 1 : c;
    return c;
}

__device__ __forceinline__ void bin_insert(float px, float py, int id) {
    int b = cell_coord(py) * GG + cell_coord(px);
    int s = atomicAdd(&g_cnt[b], 1);
    if (s < CAP) g_pts[b * CAP + s] = make_float4(px, py, __int_as_float(id), 0.0f);
}

// ---------------------------------------------------------------------------
__global__ void k_copy_in(const float* __restrict__ src) {
    int i = blockIdx.x * blockDim.x + threadIdx.x;
    if (i < N_PTS * C_DIM) g_x[i] = src[i];
    if (i < GG * GG) g_cnt[i] = 0;
}

__global__ void k_binfill() {
    int i = blockIdx.x * blockDim.x + threadIdx.x;
    if (i >= N_PTS) return;
    bin_insert(g_x[i * C_DIM + 0], g_x[i * C_DIM + 1], i);
}

// ---------------------------------------------------------------------------
// Warp-per-query kNN, lane-parallel ring scan:
//  - lanes probe up to 32 ring cells' counts at once (batched, not serial)
//  - non-empty cells broadcast via ballot+shfl; all 32 lanes split the points
//  - per-lane sorted top-9 in registers; warp-count termination; u64 merge.
__global__ void __launch_bounds__(256) k_knn() {
    int gtid = blockIdx.x * blockDim.x + threadIdx.x;
    int q    = gtid >> 5;
    int lane = gtid & 31;
    if (q >= N_PTS) return;

    const float qx = g_x[q * C_DIM + 0];
    const float qy = g_x[q * C_DIM + 1];
    const int cx = cell_coord(qx);
    const int cy = cell_coord(qy);

    const float INF = __int_as_float(0x7f800000);
    float bd[KNN];
    int   bi[KNN];
#pragma unroll
    for (int p = 0; p < KNN; ++p) { bd[p] = INF; bi[p] = q; }

    auto process_pts = [&](int b, int cnt) {
        const float4* pp = &g_pts[b * CAP];
        for (int t = lane; t < cnt; t += 32) {
            float4 p = pp[t];
            float dx = qx - p.x;
            float dy = qy - p.y;
            float d2 = __fadd_rn(__fmul_rn(dx, dx), __fmul_rn(dy, dy));
            if (d2 < bd[KNN - 1]) {
                float cd = d2;
                int   ci = __float_as_int(p.z);
#pragma unroll
                for (int pos = 0; pos < KNN; ++pos) {
                    if (cd < bd[pos]) {
                        float tf = bd[pos]; bd[pos] = cd; cd = tf;
                        int   ti = bi[pos]; bi[pos] = ci; ci = ti;
                    }
                }
            }
        }
    };

    // r = 0: center cell (uniform across warp)
    {
        int b = cy * GG + cx;
        int cnt = g_cnt[b];
        cnt = cnt < CAP ? cnt : CAP;
        process_pts(b, cnt);
    }

    for (int r = 1; r < GG; ++r) {
        int nc = 8 * r;                    // cells in Chebyshev ring r
        for (int base = 0; base < nc; base += 32) {
            int i = base + lane;
            int xx = 0, yy = 0;
            bool ok = (i < nc);
            if (ok) {
                int side = 2 * r + 1;
                if (i < side)            { xx = cx - r + i;          yy = cy - r; }
                else if (i < 2 * side)   { xx = cx - r + (i - side); yy = cy + r; }
                else {
                    int j = i - 2 * side;          // 0 .. 4r-3
                    int m = 2 * r - 1;
                    xx = (j < m) ? (cx - r) : (cx + r);
                    yy = cy - r + 1 + (j < m ? j : j - m);
                }
                ok = (xx >= 0) & (xx < GG) & (yy >= 0) & (yy < GG);
            }
            int b = yy * GG + xx;
            int cnt = 0;
            if (ok) {
                cnt = g_cnt[b];
                cnt = cnt < CAP ? cnt : CAP;
            }
            unsigned mask = __ballot_sync(0xffffffffu, cnt > 0);
            while (mask) {
                int s = __ffs(mask) - 1;
                mask &= mask - 1;
                int bb = __shfl_sync(0xffffffffu, b,   s);
                int cc = __shfl_sync(0xffffffffu, cnt, s);
                process_pts(bb, cc);
            }
        }
        // Terminate when >= KNN warp-wide candidates lie within rim = r*CS:
        // then the true 9th-nearest <= rim, and all unvisited cells are > rim.
        float rim = (float)r * CS;
        float rim2 = rim * rim;
        int c = 0;
#pragma unroll
        for (int p = 0; p < KNN; ++p) c += (bd[p] <= rim2) ? 1 : 0;
#pragma unroll
        for (int off = 16; off > 0; off >>= 1)
            c += __shfl_xor_sync(0xffffffffu, c, off);
        if (c >= KNN) break;
    }

    // Merge 32 sorted local lists -> global top-9 (u64 min-reduce x9).
#pragma unroll
    for (int sel = 0; sel < KNN; ++sel) {
        unsigned long long pack =
            ((unsigned long long)__float_as_uint(bd[0]) << 32) | (unsigned)bi[0];
        unsigned long long m = pack;
#pragma unroll
        for (int off = 16; off > 0; off >>= 1) {
            unsigned long long o = __shfl_xor_sync(0xffffffffu, m, off);
            m = o < m ? o : m;
        }
        unsigned matched = __ballot_sync(0xffffffffu, pack == m);
        if (lane == __ffs(matched) - 1) {
#pragma unroll
            for (int p = 0; p < KNN - 1; ++p) { bd[p] = bd[p + 1]; bi[p] = bi[p + 1]; }
            bd[KNN - 1] = INF;
            bi[KNN - 1] = q;
        }
        if (lane == 0) g_idx[q * KNN + sel] = (int)(unsigned)(m & 0xffffffffu);
    }
}

// ---------------------------------------------------------------------------
// GCN layer, 4 threads per node. Each sub-thread gathers CIN/4 channels of
// the 9 neighbors, computes partial products into acc[COUT], then a
// reduce-scatter over shfl_xor(1), shfl_xor(2) leaves each sub-thread with
// its contiguous COUT/4 output slice (all register indexing compile-time).
template <int CIN, int COUT, bool RELU, bool UPD, bool ZERO, bool BINFILL, bool WOUT>
__global__ void __launch_bounds__(128) k_layer(const float* __restrict__ hin,
                                               const float* __restrict__ W,
                                               float* __restrict__ hout,
                                               float* __restrict__ out2) {
    constexpr int CPT = CIN / 4;    // input channels per sub-thread
    constexpr int HLF = COUT / 2;
    constexpr int QTR = COUT / 4;

    __shared__ float sW[CIN * COUT];
    for (int i = threadIdx.x; i < CIN * COUT; i += blockDim.x) sW[i] = W[i];
    __syncthreads();

    int t   = blockIdx.x * blockDim.x + threadIdx.x;
    int n   = t >> 2;
    int sub = t & 3;

    if (ZERO && t < GG * GG) g_cnt[t] = 0;

    // Gather + mean over this sub-thread's channel slice
    float agg[CPT];
#pragma unroll
    for (int c = 0; c < CPT; ++c) agg[c] = 0.0f;

    const int* ip = g_idx + n * KNN;
#pragma unroll
    for (int k = 0; k < KNN; ++k) {
        int nb = __ldg(&ip[k]);
        const float4* row = (const float4*)(hin + nb * CIN + sub * CPT);
#pragma unroll
        for (int c4 = 0; c4 < CPT / 4; ++c4) {
            float4 v = row[c4];
            agg[4 * c4 + 0] += v.x;
            agg[4 * c4 + 1] += v.y;
            agg[4 * c4 + 2] += v.z;
            agg[4 * c4 + 3] += v.w;
        }
    }
#pragma unroll
    for (int c = 0; c < CPT; ++c) agg[c] *= (1.0f / 9.0f);

    // Partial matmul over my channel slice
    float acc[COUT];
#pragma unroll
    for (int j = 0; j < COUT; ++j) acc[j] = 0.0f;
#pragma unroll
    for (int cl = 0; cl < CPT; ++cl) {
        float a = agg[cl];
        const float* wrow = &sW[(sub * CPT + cl) * COUT];
#pragma unroll
        for (int j = 0; j < COUT; ++j) acc[j] = fmaf(a, wrow[j], acc[j]);
    }

    // Reduce-scatter across the 4 sub-threads (static register indexing only)
    bool b0 = (sub & 1) != 0;
    bool b1 = (sub & 2) != 0;
    float h1[HLF];
#pragma unroll
    for (int j = 0; j < HLF; ++j) {
        float keep = b0 ? acc[HLF + j] : acc[j];
        float send = b0 ? acc[j]       : acc[HLF + j];
        h1[j] = keep + __shfl_xor_sync(0xffffffffu, send, 1);
    }
    float h2[QTR];
#pragma unroll
    for (int j = 0; j < QTR; ++j) {
        float keep = b1 ? h1[QTR + j] : h1[j];
        float send = b1 ? h1[j]       : h1[QTR + j];
        h2[j] = keep + __shfl_xor_sync(0xffffffffu, send, 2);
    }
    int jbase = (b0 ? HLF : 0) + (b1 ? QTR : 0);

    float* outp = hout + n * COUT + jbase;
    float nx = 0.0f, ny = 0.0f;
#pragma unroll
    for (int v4 = 0; v4 < QTR / 4; ++v4) {
        float4 r;
        r.x = h2[4 * v4 + 0];
        r.y = h2[4 * v4 + 1];
        r.z = h2[4 * v4 + 2];
        r.w = h2[4 * v4 + 3];
        if (RELU) {
            r.x = fmaxf(r.x, 0.0f); r.y = fmaxf(r.y, 0.0f);
            r.z = fmaxf(r.z, 0.0f); r.w = fmaxf(r.w, 0.0f);
        }
        if (UPD) {
            float4 old = ((const float4*)outp)[v4];
            r.x = fmaf(r.x, UPD_RATE, old.x);
            r.y = fmaf(r.y, UPD_RATE, old.y);
            r.z = fmaf(r.z, UPD_RATE, old.z);
            r.w = fmaf(r.w, UPD_RATE, old.w);
        }
        ((float4*)outp)[v4] = r;
        if (WOUT) ((float4*)(out2 + n * COUT + jbase))[v4] = r;
        if (BINFILL && v4 == 0 && jbase == 0) { nx = r.x; ny = r.y; }
    }
    if (BINFILL && jbase == 0) bin_insert(nx, ny, n);
}

// ---------------------------------------------------------------------------
extern "C" void kernel_launch(void* const* d_in, const int* in_sizes, int n_in,
                              void* d_out, int out_size) {
    const float* seed = (const float*)d_in[0];
    const float* W1   = (const float*)d_in[1];
    const float* W2   = (const float*)d_in[2];
    const float* W3   = (const float*)d_in[3];
    const float* W4   = (const float*)d_in[4];
    float* out = (float*)d_out;

    float *px, *pha, *phb;
    cudaGetSymbolAddress((void**)&px,  g_x);
    cudaGetSymbolAddress((void**)&pha, g_ha);
    cudaGetSymbolAddress((void**)&phb, g_hb);

    constexpr int LGRID = (N_PTS * 4) / 128;

    // step 0
    k_copy_in<<<(N_PTS * C_DIM + 255) / 256, 256>>>(seed);   // + zero counts
    k_binfill<<<N_PTS / 256, 256>>>();
    k_knn<<<(N_PTS * 32) / 256, 256>>>();
    k_layer<16, 32, true,  false, false, false, false><<<LGRID, 128>>>(px,  W1, pha, nullptr);
    k_layer<32, 32, true,  false, false, false, false><<<LGRID, 128>>>(pha, W2, phb, nullptr);
    k_layer<32, 32, true,  false, true,  false, false><<<LGRID, 128>>>(phb, W3, pha, nullptr); // zero counts for step 1
    k_layer<32, 16, false, true,  false, true,  false><<<LGRID, 128>>>(pha, W4, px,  nullptr); // x += ; bin new coords

    // step 1
    k_knn<<<(N_PTS * 32) / 256, 256>>>();
    k_layer<16, 32, true,  false, false, false, false><<<LGRID, 128>>>(px,  W1, pha, nullptr);
    k_layer<32, 32, true,  false, false, false, false><<<LGRID, 128>>>(pha, W2, phb, nullptr);
    k_layer<32, 32, true,  false, false, false, false><<<LGRID, 128>>>(phb, W3, pha, nullptr);
    k_layer<32, 16, false, true,  false, false, true ><<<LGRID, 128>>>(pha, W4, px,  out);     // x += ; writeout
}